// round 5
// baseline (speedup 1.0000x reference)
#include <cuda_runtime.h>
#include <cstdint>
#include <math.h>

#define BATCH 2048
#define TT 64
#define EE 256
#define SCALE 0.125f
#define FK  16384
#define SPLITK 8
#define KSPL (FK / SPLITK)          // 2048

// ------------------------------------------------------------------
// scratch (static __device__ — no allocations allowed)
// ------------------------------------------------------------------
__device__ float g_x[BATCH * TT * EE];              // attn + query (134MB)
__device__ float g_partial[SPLITK * BATCH * 256];   // 16MB

// ------------------------------------------------------------------
// packed f32x2 helpers (FFMA2 — only reachable via PTX fma.rn.f32x2)
// ------------------------------------------------------------------
__device__ __forceinline__ void ffma2(uint64_t& d, uint64_t a, uint64_t b) {
    asm("fma.rn.f32x2 %0, %1, %2, %0;" : "+l"(d) : "l"(a), "l"(b));
}
__device__ __forceinline__ uint64_t dupf(float x) {
    uint64_t d; asm("mov.b64 %0, {%1, %1};" : "=l"(d) : "f"(x)); return d;
}
__device__ __forceinline__ void unpack2(uint64_t d, float& lo, float& hi) {
    asm("mov.b64 {%0, %1}, %2;" : "=f"(lo), "=f"(hi) : "l"(d));
}
__device__ __forceinline__ uint32_t smem_u32(const void* p) {
    uint32_t a;
    asm("{ .reg .u64 t; cvta.to.shared.u64 t, %1; cvt.u32.u64 %0, t; }" : "=r"(a) : "l"(p));
    return a;
}
#define CP_ASYNC16(dst, src) \
    asm volatile("cp.async.cg.shared.global [%0], [%1], 16;" :: "r"(dst), "l"(src) : "memory")
#define CP_ASYNC_WAIT_ALL() \
    asm volatile("cp.async.wait_all;" ::: "memory")

// ------------------------------------------------------------------
// attention kernel, 512 threads (+ writes x = attn + query to g_x)
// ------------------------------------------------------------------
#define QT_PITCH 68
#define S_PITCH  66   // EVEN: float2 stores at row*S_PITCH + 2*lane stay 8B-aligned
#define SM_QT (EE * QT_PITCH)
#define SM_KT (EE * QT_PITCH)
#define SM_V  (TT * EE)
#define SM_S  (TT * S_PITCH)
#define ATTN_SMEM_BYTES ((SM_QT + SM_KT + SM_V + SM_S) * 4)

__global__ __launch_bounds__(512, 1)
void attn_kernel(const float* __restrict__ Qg, const float* __restrict__ Kg,
                 const float* __restrict__ Vg, float* __restrict__ Ag)
{
    extern __shared__ float sm[];
    float* QT = sm;                 // [256][68] transposed
    float* KT = QT + SM_QT;         // [256][68] transposed
    float* Vv = KT + SM_KT;         // [64][256] row-major
    float* Ss = Vv + SM_V;          // [64][66]

    const int tid = threadIdx.x;
    const int b   = blockIdx.x;
    const size_t base = (size_t)b * TT * EE;
    const float* qb = Qg + base;
    const float* kb = Kg + base;
    const float* vb = Vg + base;

    // V: direct row-major copy via cp.async (8 x 16B per thread)
    {
        const uint32_t vsm = smem_u32(Vv);
        #pragma unroll
        for (int j = 0; j < 8; ++j) {
            const int f4 = tid + j * 512;               // 4096 float4 total
            CP_ASYNC16(vsm + f4 * 16, (const float4*)vb + f4);
        }
    }

    // Q,K transposed: e = tid&255, half h = tid>>8 covers 32 rows
    {
        const int e = tid & 255;
        const int h = tid >> 8;
        #pragma unroll 8
        for (int i = h * 32; i < h * 32 + 32; ++i) {
            QT[e * QT_PITCH + i] = qb[i * EE + e];
            KT[e * QT_PITCH + i] = kb[i * EE + e];
        }
    }
    CP_ASYNC_WAIT_ALL();
    __syncthreads();

    // ---- S = Q @ K^T : 4q x 2k per thread (512 threads) ----
    const int txs = tid & 31;   // k-pair index (cols txs*2, txs*2+1)
    const int tys = tid >> 5;   // q group (rows tys*4..+3)

    uint64_t accS[4];
    #pragma unroll
    for (int i = 0; i < 4; ++i) accS[i] = 0ull;

    #pragma unroll 4
    for (int e = 0; e < EE; ++e) {
        float4 qv = *(const float4*)&QT[e * QT_PITCH + tys * 4];   // broadcast per warp
        uint64_t kp = *(const uint64_t*)&KT[e * QT_PITCH + txs * 2];
        ffma2(accS[0], dupf(qv.x), kp);
        ffma2(accS[1], dupf(qv.y), kp);
        ffma2(accS[2], dupf(qv.z), kp);
        ffma2(accS[3], dupf(qv.w), kp);
    }
    #pragma unroll
    for (int i = 0; i < 4; ++i) {
        float s0, s1;
        unpack2(accS[i], s0, s1);
        float2* sp = (float2*)&Ss[(tys * 4 + i) * S_PITCH + txs * 2];
        *sp = make_float2(s0, s1);
    }
    __syncthreads();

    // ---- softmax: 16 warps x 4 rows ----
    const int warp = tid >> 5, lane = tid & 31;
    #pragma unroll
    for (int rr = 0; rr < 4; ++rr) {
        const int r = warp * 4 + rr;
        float v1 = Ss[r * S_PITCH + lane]      * SCALE;
        float v2 = Ss[r * S_PITCH + lane + 32] * SCALE;
        float m = fmaxf(v1, v2);
        #pragma unroll
        for (int o = 16; o > 0; o >>= 1)
            m = fmaxf(m, __shfl_xor_sync(0xffffffffu, m, o));
        float e1 = expf(v1 - m);
        float e2 = expf(v2 - m);
        float s = e1 + e2;
        #pragma unroll
        for (int o = 16; o > 0; o >>= 1)
            s += __shfl_xor_sync(0xffffffffu, s, o);
        float inv = 1.0f / s;
        Ss[r * S_PITCH + lane]      = e1 * inv;
        Ss[r * S_PITCH + lane + 32] = e2 * inv;
    }
    __syncthreads();

    // ---- A = S @ V : 4q x 8e per thread ----
    const int txa = tid & 31;   // e block (cols txa*8..+7)
    const int tya = tid >> 5;   // q group (rows tya*4..+3)

    uint64_t accA[4][4];        // [q][e-pair]
    #pragma unroll
    for (int i = 0; i < 4; ++i)
        #pragma unroll
        for (int p = 0; p < 4; ++p) accA[i][p] = 0ull;

    #pragma unroll 2
    for (int k = 0; k < TT; ++k) {
        float4 v0 = *(const float4*)&Vv[k * EE + txa * 8];
        float4 v1 = *(const float4*)&Vv[k * EE + txa * 8 + 4];
        uint64_t vp[4];
        { const uint64_t* u = (const uint64_t*)&v0; vp[0] = u[0]; vp[1] = u[1]; }
        { const uint64_t* u = (const uint64_t*)&v1; vp[2] = u[0]; vp[3] = u[1]; }
        #pragma unroll
        for (int i = 0; i < 4; ++i) {
            uint64_t sd = dupf(Ss[(tya * 4 + i) * S_PITCH + k]);   // broadcast
            #pragma unroll
            for (int p = 0; p < 4; ++p) ffma2(accA[i][p], sd, vp[p]);
        }
    }

    // epilogue: attn -> Ag, x = attn + query(global) -> g_x
    float* ab = Ag + base;
    float* xb = g_x + base;
    #pragma unroll
    for (int i = 0; i < 4; ++i) {
        const int qrow = tya * 4 + i;
        const int e0 = txa * 8;
        float4 o0, o1;
        unpack2(accA[i][0], o0.x, o0.y);
        unpack2(accA[i][1], o0.z, o0.w);
        unpack2(accA[i][2], o1.x, o1.y);
        unpack2(accA[i][3], o1.z, o1.w);
        float4 q0 = *(const float4*)&qb[qrow * EE + e0];
        float4 q1 = *(const float4*)&qb[qrow * EE + e0 + 4];
        *(float4*)&ab[qrow * EE + e0]     = o0;
        *(float4*)&ab[qrow * EE + e0 + 4] = o1;
        float4 x0 = make_float4(o0.x + q0.x, o0.y + q0.y, o0.z + q0.z, o0.w + q0.w);
        float4 x1 = make_float4(o1.x + q1.x, o1.y + q1.y, o1.z + q1.z, o1.w + q1.w);
        *(float4*)&xb[qrow * EE + e0]     = x0;
        *(float4*)&xb[qrow * EE + e0 + 4] = x1;
    }
}

// ------------------------------------------------------------------
// FF GEMM: partial[s][m][n] = g_x[m, s-range] @ W^T   (FFMA2 SIMT)
// grid (16, 4, 8), 256 threads, BM=128 BN=64 BK=16, 8x4 tile, acc packed over m
// ------------------------------------------------------------------
#define FBM 128
#define FBN 64
#define FBK 16
#define XP 132           // Xs pitch (floats)
#define WP 68            // Ws pitch
#define NTILE (KSPL / FBK)   // 128

__global__ __launch_bounds__(256, 3)
void ff2_kernel(const float* __restrict__ Wg)
{
    __shared__ float Xs[2][FBK][XP];
    __shared__ float Ws[2][FBK][WP];

    const int tid = threadIdx.x;
    const int m0 = blockIdx.x * FBM;
    const int n0 = blockIdx.y * FBN;
    const size_t kbase = (size_t)blockIdx.z * KSPL;

    // loader mapping: float4 f -> row f>>2, kcol (f&3)*4
    const int lrow = tid >> 2;          // 0..63
    const int lc   = (tid & 3) * 4;     // 0,4,8,12
    const float* xp0 = g_x + (size_t)(m0 + lrow) * FK + kbase + lc;        // rows 0..63
    const float* xp1 = g_x + (size_t)(m0 + 64 + lrow) * FK + kbase + lc;   // rows 64..127
    const float* wpt = Wg  + (size_t)(n0 + lrow) * FK + kbase + lc;

    // compute mapping: 8m x 4n per thread
    const int tx = tid & 15;    // n: cols tx*4..+3
    const int ty = tid >> 4;    // m: rows ty*8..+7

    uint64_t acc[4][4];         // [m-pair][n]
    #pragma unroll
    for (int mp = 0; mp < 4; ++mp)
        #pragma unroll
        for (int j = 0; j < 4; ++j) acc[mp][j] = 0ull;

    // prologue: stage tile 0
    float4 xA = *(const float4*)xp0;
    float4 xB = *(const float4*)xp1;
    float4 wA = *(const float4*)wpt;

    for (int t = 0; t < NTILE; ++t) {
        const int buf = t & 1;
        // commit staged regs -> smem (transposed)
        {
            const float* a0 = (const float*)&xA;
            const float* a1 = (const float*)&xB;
            const float* w0 = (const float*)&wA;
            #pragma unroll
            for (int j = 0; j < 4; ++j) {
                Xs[buf][lc + j][lrow]      = a0[j];
                Xs[buf][lc + j][lrow + 64] = a1[j];
                Ws[buf][lc + j][lrow]      = w0[j];
            }
        }
        __syncthreads();

        // prefetch next tile
        if (t + 1 < NTILE) {
            const size_t kt = (size_t)(t + 1) * FBK;
            xA = *(const float4*)(xp0 + kt);
            xB = *(const float4*)(xp1 + kt);
            wA = *(const float4*)(wpt + kt);
        }

        // compute
        #pragma unroll
        for (int k = 0; k < FBK; ++k) {
            float4 a0 = *(const float4*)&Xs[buf][k][ty * 8];
            float4 a1 = *(const float4*)&Xs[buf][k][ty * 8 + 4];
            float4 bv = *(const float4*)&Ws[buf][k][tx * 4];
            uint64_t ap[4];
            { const uint64_t* u = (const uint64_t*)&a0; ap[0] = u[0]; ap[1] = u[1]; }
            { const uint64_t* u = (const uint64_t*)&a1; ap[2] = u[0]; ap[3] = u[1]; }
            const float bb[4] = {bv.x, bv.y, bv.z, bv.w};
            #pragma unroll
            for (int j = 0; j < 4; ++j) {
                uint64_t bd = dupf(bb[j]);
                #pragma unroll
                for (int mp = 0; mp < 4; ++mp) ffma2(acc[mp][j], ap[mp], bd);
            }
        }
        __syncthreads();
    }

    // epilogue: unpack (acc packed over m) and store partials
    #pragma unroll
    for (int mp = 0; mp < 4; ++mp) {
        float lo[4], hi[4];
        #pragma unroll
        for (int j = 0; j < 4; ++j) unpack2(acc[mp][j], lo[j], hi[j]);
        const int mlo = m0 + ty * 8 + mp * 2;
        float* p0 = g_partial + ((size_t)blockIdx.z * BATCH + mlo) * 256 + n0 + tx * 4;
        float* p1 = p0 + 256;
        *(float4*)p0 = make_float4(lo[0], lo[1], lo[2], lo[3]);
        *(float4*)p1 = make_float4(hi[0], hi[1], hi[2], hi[3]);
    }
}

// ------------------------------------------------------------------
// reduce: out = relu(sum_s partial + bias)
// ------------------------------------------------------------------
__global__ __launch_bounds__(256)
void reduce_kernel(const float* __restrict__ bias, float* __restrict__ out)
{
    const int g = blockIdx.x * 256 + threadIdx.x;   // float4 index
    const int m = g >> 6;
    const int nc = g & 63;
    float4 acc = ((const float4*)bias)[nc];
    #pragma unroll
    for (int ks = 0; ks < SPLITK; ++ks) {
        float4 p = ((const float4*)g_partial)[((size_t)ks * BATCH + m) * 64 + nc];
        acc.x += p.x; acc.y += p.y; acc.z += p.z; acc.w += p.w;
    }
    acc.x = fmaxf(acc.x, 0.0f); acc.y = fmaxf(acc.y, 0.0f);
    acc.z = fmaxf(acc.z, 0.0f); acc.w = fmaxf(acc.w, 0.0f);
    ((float4*)out)[(size_t)m * 64 + nc] = acc;
}

// ------------------------------------------------------------------
// launch
// ------------------------------------------------------------------
extern "C" void kernel_launch(void* const* d_in, const int* in_sizes, int n_in,
                              void* d_out, int out_size)
{
    const float* value = (const float*)d_in[0];
    const float* key_  = (const float*)d_in[1];
    const float* query = (const float*)d_in[2];
    const float* W_ff  = (const float*)d_in[4];
    const float* b_ff  = (const float*)d_in[5];

    float* out  = (float*)d_out;                 // [2048, 256]
    float* attn = out + (size_t)BATCH * 256;     // [2048, 64, 256]

    cudaFuncSetAttribute(attn_kernel,
                         cudaFuncAttributeMaxDynamicSharedMemorySize, ATTN_SMEM_BYTES);

    attn_kernel<<<BATCH, 512, ATTN_SMEM_BYTES>>>(query, key_, value, attn);
    ff2_kernel<<<dim3(16, 4, SPLITK), 256>>>(W_ff);
    reduce_kernel<<<512, 256>>>(b_ff, out);
}

// round 6
// speedup vs baseline: 1.3883x; 1.3883x over previous
#include <cuda_runtime.h>
#include <cstdint>
#include <math.h>

#define BATCH 2048
#define TT 64
#define EE 256
#define SCALE 0.125f
#define FK  16384
#define SPLITK 8
#define KSPL (FK / SPLITK)          // 2048

// ------------------------------------------------------------------
// scratch (static __device__ — no allocations allowed)
// ------------------------------------------------------------------
__device__ float g_x[BATCH * TT * EE];              // attn + query (134MB)
__device__ float g_partial[SPLITK * BATCH * 256];   // 16MB

// ------------------------------------------------------------------
// packed f32x2 helpers (FFMA2 — only reachable via PTX fma.rn.f32x2)
// ------------------------------------------------------------------
__device__ __forceinline__ void ffma2(uint64_t& d, uint64_t a, uint64_t b) {
    asm("fma.rn.f32x2 %0, %1, %2, %0;" : "+l"(d) : "l"(a), "l"(b));
}
__device__ __forceinline__ uint64_t dupf(float x) {
    uint64_t d; asm("mov.b64 %0, {%1, %1};" : "=l"(d) : "f"(x)); return d;
}
__device__ __forceinline__ void unpack2(uint64_t d, float& lo, float& hi) {
    asm("mov.b64 {%0, %1}, %2;" : "=f"(lo), "=f"(hi) : "l"(d));
}

// ------------------------------------------------------------------
// attention kernel, 256 threads (R3 layout; epilogue reads q from global)
// ------------------------------------------------------------------
#define QT_PITCH 68
#define S_PITCH  65
#define SM_QT (EE * QT_PITCH)
#define SM_KT (EE * QT_PITCH)
#define SM_V  (TT * EE)
#define SM_S  (TT * S_PITCH)
#define ATTN_SMEM_BYTES ((SM_QT + SM_KT + SM_V + SM_S) * 4)

__global__ __launch_bounds__(256, 1)
void attn_kernel(const float* __restrict__ Qg, const float* __restrict__ Kg,
                 const float* __restrict__ Vg, float* __restrict__ Ag)
{
    extern __shared__ float sm[];
    float* QT = sm;                 // [256][68] transposed
    float* KT = QT + SM_QT;         // [256][68] transposed
    float* Vv = KT + SM_KT;         // [64][256] row-major
    float* Ss = Vv + SM_V;          // [64][65]

    const int tid = threadIdx.x;
    const int b   = blockIdx.x;
    const size_t base = (size_t)b * TT * EE;
    const float* qb = Qg + base;
    const float* kb = Kg + base;
    const float* vb = Vg + base;

    #pragma unroll 4
    for (int i = 0; i < TT; ++i) {
        QT[tid * QT_PITCH + i] = qb[i * EE + tid];
        KT[tid * QT_PITCH + i] = kb[i * EE + tid];
        Vv[i * EE + tid]       = vb[i * EE + tid];
    }
    __syncthreads();

    const int tx = tid & 15;
    const int ty = tid >> 4;

    // ---- S = Q @ K^T : FFMA2, 4 rows x 2 col-pairs per thread ----
    uint64_t acc2[4][2];
    #pragma unroll
    for (int i = 0; i < 4; ++i) { acc2[i][0] = 0ull; acc2[i][1] = 0ull; }

    const float4* QT4 = (const float4*)QT;
    const float4* KT4 = (const float4*)KT;
    #pragma unroll 4
    for (int e = 0; e < EE; ++e) {
        float4 qv = QT4[e * (QT_PITCH / 4) + ty];
        float4 kv = KT4[e * (QT_PITCH / 4) + tx];
        const uint64_t* kp = (const uint64_t*)&kv;
        const float qa[4] = {qv.x, qv.y, qv.z, qv.w};
        #pragma unroll
        for (int i = 0; i < 4; ++i) {
            uint64_t qd = dupf(qa[i]);
            ffma2(acc2[i][0], qd, kp[0]);
            ffma2(acc2[i][1], qd, kp[1]);
        }
    }
    #pragma unroll
    for (int i = 0; i < 4; ++i) {
        float s0, s1, s2, s3;
        unpack2(acc2[i][0], s0, s1);
        unpack2(acc2[i][1], s2, s3);
        float* sr = &Ss[(ty * 4 + i) * S_PITCH + tx * 4];
        sr[0] = s0; sr[1] = s1; sr[2] = s2; sr[3] = s3;
    }
    __syncthreads();

    // ---- softmax ----
    const int warp = tid >> 5, lane = tid & 31;
    #pragma unroll
    for (int rr = 0; rr < 8; ++rr) {
        const int r = warp * 8 + rr;
        float v1 = Ss[r * S_PITCH + lane]      * SCALE;
        float v2 = Ss[r * S_PITCH + lane + 32] * SCALE;
        float m = fmaxf(v1, v2);
        #pragma unroll
        for (int o = 16; o > 0; o >>= 1)
            m = fmaxf(m, __shfl_xor_sync(0xffffffffu, m, o));
        float e1 = expf(v1 - m);
        float e2 = expf(v2 - m);
        float s = e1 + e2;
        #pragma unroll
        for (int o = 16; o > 0; o >>= 1)
            s += __shfl_xor_sync(0xffffffffu, s, o);
        float inv = 1.0f / s;
        Ss[r * S_PITCH + lane]      = e1 * inv;
        Ss[r * S_PITCH + lane + 32] = e2 * inv;
    }
    __syncthreads();

    // ---- prefetch q rows from GLOBAL (hidden under A-phase compute) ----
    float4 qpre[4][4];
    #pragma unroll
    for (int i = 0; i < 4; ++i)
        #pragma unroll
        for (int eb = 0; eb < 4; ++eb)
            qpre[i][eb] = *(const float4*)&qb[(ty * 4 + i) * EE + eb * 64 + tx * 4];

    // ---- A = S @ V : FFMA2, 4 rows x (4 eb x 2 pairs) per thread ----
    uint64_t accA2[4][4][2];
    #pragma unroll
    for (int i = 0; i < 4; ++i)
        #pragma unroll
        for (int eb = 0; eb < 4; ++eb) { accA2[i][eb][0] = 0ull; accA2[i][eb][1] = 0ull; }

    const float4* V4 = (const float4*)Vv;
    #pragma unroll 2
    for (int k = 0; k < TT; ++k) {
        uint64_t vp[4][2];
        #pragma unroll
        for (int eb = 0; eb < 4; ++eb) {
            float4 vv = V4[k * (EE / 4) + eb * 16 + tx];
            const uint64_t* u = (const uint64_t*)&vv;
            vp[eb][0] = u[0]; vp[eb][1] = u[1];
        }
        #pragma unroll
        for (int i = 0; i < 4; ++i) {
            uint64_t sd = dupf(Ss[(ty * 4 + i) * S_PITCH + k]);
            #pragma unroll
            for (int eb = 0; eb < 4; ++eb) {
                ffma2(accA2[i][eb][0], sd, vp[eb][0]);
                ffma2(accA2[i][eb][1], sd, vp[eb][1]);
            }
        }
    }

    float* ab = Ag + base;
    float* xb = g_x + base;
    #pragma unroll
    for (int i = 0; i < 4; ++i) {
        const int qrow = ty * 4 + i;
        #pragma unroll
        for (int eb = 0; eb < 4; ++eb) {
            float4 o;
            unpack2(accA2[i][eb][0], o.x, o.y);
            unpack2(accA2[i][eb][1], o.z, o.w);
            const int e0 = eb * 64 + tx * 4;
            float4 q = qpre[i][eb];
            float4 x = make_float4(o.x + q.x, o.y + q.y, o.z + q.z, o.w + q.w);
            *(float4*)&ab[qrow * EE + e0] = o;
            *(float4*)&xb[qrow * EE + e0] = x;
        }
    }
}

// ------------------------------------------------------------------
// FF GEMM: partial[s][m][n] = g_x[m, s-range] @ W^T   (FFMA2 SIMT)
// 256 threads, BM=128 BN=128 BK=16, 8x8 tile, W stored DUPLICATED in
// smem (pairs), so the hot loop has zero dup-MOVs.
// grid (16, 2, SPLITK), 2 CTAs/SM.
// ------------------------------------------------------------------
#define FBM 128
#define FBN 128
#define FBK 16
#define XP 132                  // Xs row pitch (floats)
#define WBLK 20                 // words per n-block: 8 n dup'd (16) + 4 pad
#define WROW (16 * WBLK)        // 320 words per k-row
#define XS_WORDS (2 * FBK * XP)     // 4224
#define WD_WORDS (2 * FBK * WROW)   // 10240
#define FF_SMEM_BYTES ((XS_WORDS + WD_WORDS) * 4)   // 57856
#define NTILE (KSPL / FBK)      // 128

__global__ __launch_bounds__(256, 2)
void ff2_kernel(const float* __restrict__ Wg)
{
    extern __shared__ float fsm[];
    float* Xs = fsm;                  // [2][16][132]
    float* Wd = fsm + XS_WORDS;       // [2][16][320]

    const int tid = threadIdx.x;
    const int m0 = blockIdx.x * FBM;
    const int n0 = blockIdx.y * FBN;
    const size_t kbase = (size_t)blockIdx.z * KSPL;

    // loader mapping: float4 f -> row lrow (and +64), kcol lc..lc+3
    const int lrow = tid >> 2;          // 0..63
    const int lc   = (tid & 3) * 4;     // 0,4,8,12
    const float* xp0 = g_x + (size_t)(m0 + lrow) * FK + kbase + lc;
    const float* xp1 = g_x + (size_t)(m0 + 64 + lrow) * FK + kbase + lc;
    const float* wp0 = Wg  + (size_t)(n0 + lrow) * FK + kbase + lc;
    const float* wp1 = Wg  + (size_t)(n0 + 64 + lrow) * FK + kbase + lc;

    // W dup-store word offsets within a k-row
    const int wa_off = WBLK * (lrow >> 3) + 2 * (lrow & 7);
    const int wb_off = WBLK * (8 + (lrow >> 3)) + 2 * (lrow & 7);

    // compute mapping: 8m x 8n per thread
    const int tx = tid & 15;    // n block: cols tx*8..+7
    const int ty = tid >> 4;    // m rows ty*8..+7

    uint64_t acc[4][8];         // [m-pair][n]
    #pragma unroll
    for (int mp = 0; mp < 4; ++mp)
        #pragma unroll
        for (int n = 0; n < 8; ++n) acc[mp][n] = 0ull;

    // prologue: stage tile 0
    float4 xA = *(const float4*)xp0;
    float4 xB = *(const float4*)xp1;
    float4 wA = *(const float4*)wp0;
    float4 wB = *(const float4*)wp1;

    for (int t = 0; t < NTILE; ++t) {
        const int buf = t & 1;
        float* Xb = Xs + buf * FBK * XP;
        float* Wb = Wd + buf * FBK * WROW;
        // commit staged regs -> smem
        {
            const float* a0 = (const float*)&xA;
            const float* a1 = (const float*)&xB;
            const float* w0 = (const float*)&wA;
            const float* w1 = (const float*)&wB;
            #pragma unroll
            for (int j = 0; j < 4; ++j) {
                Xb[(lc + j) * XP + lrow]      = a0[j];
                Xb[(lc + j) * XP + lrow + 64] = a1[j];
                *(uint64_t*)&Wb[(lc + j) * WROW + wa_off] = dupf(w0[j]);
                *(uint64_t*)&Wb[(lc + j) * WROW + wb_off] = dupf(w1[j]);
            }
        }
        __syncthreads();

        // prefetch next tile
        if (t + 1 < NTILE) {
            const size_t kt = (size_t)(t + 1) * FBK;
            xA = *(const float4*)(xp0 + kt);
            xB = *(const float4*)(xp1 + kt);
            wA = *(const float4*)(wp0 + kt);
            wB = *(const float4*)(wp1 + kt);
        }

        // compute
        #pragma unroll
        for (int k = 0; k < FBK; ++k) {
            const float* xr = Xb + k * XP + ty * 8;
            float4 a0 = *(const float4*)xr;
            float4 a1 = *(const float4*)(xr + 4);
            uint64_t ap[4];
            { const uint64_t* u = (const uint64_t*)&a0; ap[0] = u[0]; ap[1] = u[1]; }
            { const uint64_t* u = (const uint64_t*)&a1; ap[2] = u[0]; ap[3] = u[1]; }
            const float* wr = Wb + k * WROW + WBLK * tx;
            uint64_t bp[8];
            #pragma unroll
            for (int c = 0; c < 4; ++c) {
                float4 bv = *(const float4*)(wr + 4 * c);
                const uint64_t* u = (const uint64_t*)&bv;
                bp[2 * c]     = u[0];
                bp[2 * c + 1] = u[1];
            }
            #pragma unroll
            for (int mp = 0; mp < 4; ++mp)
                #pragma unroll
                for (int n = 0; n < 8; ++n)
                    ffma2(acc[mp][n], ap[mp], bp[n]);
        }
        __syncthreads();
    }

    // epilogue: unpack (acc packed over m) and store partials
    #pragma unroll
    for (int mp = 0; mp < 4; ++mp) {
        float lo[8], hi[8];
        #pragma unroll
        for (int n = 0; n < 8; ++n) unpack2(acc[mp][n], lo[n], hi[n]);
        const int mlo = m0 + ty * 8 + mp * 2;
        float* p0 = g_partial + ((size_t)blockIdx.z * BATCH + mlo) * 256 + n0 + tx * 8;
        float* p1 = p0 + 256;
        *(float4*)p0       = make_float4(lo[0], lo[1], lo[2], lo[3]);
        *(float4*)(p0 + 4) = make_float4(lo[4], lo[5], lo[6], lo[7]);
        *(float4*)p1       = make_float4(hi[0], hi[1], hi[2], hi[3]);
        *(float4*)(p1 + 4) = make_float4(hi[4], hi[5], hi[6], hi[7]);
    }
}

// ------------------------------------------------------------------
// reduce: out = relu(sum_s partial + bias)
// ------------------------------------------------------------------
__global__ __launch_bounds__(256)
void reduce_kernel(const float* __restrict__ bias, float* __restrict__ out)
{
    const int g = blockIdx.x * 256 + threadIdx.x;   // float4 index
    const int m = g >> 6;
    const int nc = g & 63;
    float4 acc = ((const float4*)bias)[nc];
    #pragma unroll
    for (int ks = 0; ks < SPLITK; ++ks) {
        float4 p = ((const float4*)g_partial)[((size_t)ks * BATCH + m) * 64 + nc];
        acc.x += p.x; acc.y += p.y; acc.z += p.z; acc.w += p.w;
    }
    acc.x = fmaxf(acc.x, 0.0f); acc.y = fmaxf(acc.y, 0.0f);
    acc.z = fmaxf(acc.z, 0.0f); acc.w = fmaxf(acc.w, 0.0f);
    ((float4*)out)[(size_t)m * 64 + nc] = acc;
}

// ------------------------------------------------------------------
// launch
// ------------------------------------------------------------------
extern "C" void kernel_launch(void* const* d_in, const int* in_sizes, int n_in,
                              void* d_out, int out_size)
{
    const float* value = (const float*)d_in[0];
    const float* key_  = (const float*)d_in[1];
    const float* query = (const float*)d_in[2];
    const float* W_ff  = (const float*)d_in[4];
    const float* b_ff  = (const float*)d_in[5];

    float* out  = (float*)d_out;                 // [2048, 256]
    float* attn = out + (size_t)BATCH * 256;     // [2048, 64, 256]

    cudaFuncSetAttribute(attn_kernel,
                         cudaFuncAttributeMaxDynamicSharedMemorySize, ATTN_SMEM_BYTES);
    cudaFuncSetAttribute(ff2_kernel,
                         cudaFuncAttributeMaxDynamicSharedMemorySize, FF_SMEM_BYTES);

    attn_kernel<<<BATCH, 256, ATTN_SMEM_BYTES>>>(query, key_, value, attn);
    ff2_kernel<<<dim3(16, 2, SPLITK), 256, FF_SMEM_BYTES>>>(W_ff);
    reduce_kernel<<<512, 256>>>(b_ff, out);
}

// round 8
// speedup vs baseline: 1.6107x; 1.1602x over previous
#include <cuda_runtime.h>
#include <cstdint>
#include <math.h>

#define BATCH 2048
#define TT 64
#define EE 256
#define SCALE 0.125f
#define FK  16384
#define SPLITK 8
#define KSPL (FK / SPLITK)          // 2048

// ------------------------------------------------------------------
// scratch (static __device__ — no allocations allowed)
// ------------------------------------------------------------------
__device__ float g_x[BATCH * TT * EE];              // attn + query (134MB)
__device__ float g_partial[SPLITK * BATCH * 256];   // 16MB

// ------------------------------------------------------------------
// packed f32x2 helpers (FFMA2 — only reachable via PTX fma.rn.f32x2)
// ------------------------------------------------------------------
__device__ __forceinline__ void ffma2(uint64_t& d, uint64_t a, uint64_t b) {
    asm("fma.rn.f32x2 %0, %1, %2, %0;" : "+l"(d) : "l"(a), "l"(b));
}
__device__ __forceinline__ uint64_t dupf(float x) {
    uint64_t d; asm("mov.b64 %0, {%1, %1};" : "=l"(d) : "f"(x)); return d;
}
__device__ __forceinline__ void unpack2(uint64_t d, float& lo, float& hi) {
    asm("mov.b64 {%0, %1}, %2;" : "=f"(lo), "=f"(hi) : "l"(d));
}
__device__ __forceinline__ uint32_t smem_u32(const void* p) {
    uint32_t a;
    asm("{ .reg .u64 t; cvta.to.shared.u64 t, %1; cvt.u32.u64 %0, t; }" : "=r"(a) : "l"(p));
    return a;
}
#define CP_ASYNC16(dst, src) \
    asm volatile("cp.async.cg.shared.global [%0], [%1], 16;" :: "r"(dst), "l"(src) : "memory")
#define CP_COMMIT() \
    asm volatile("cp.async.commit_group;" ::: "memory")
#define CP_WAIT(n) \
    asm volatile("cp.async.wait_group %0;" :: "n"(n) : "memory")

// ------------------------------------------------------------------
// attention kernel: 256 threads, 2 CTAs/SM.
// S-phase: e-chunked (64e, double-buffered reg pipeline).
// A-phase: k-chunked V via cp.async double buffer (overlays QT region).
// ------------------------------------------------------------------
#define EC 64                  // e-chunk
#define NEC 4
#define KC 16                  // k-chunk (V rows)
#define NKC 4
#define S_PITCH 65

// smem float offsets
#define OFF_QT 0               // [2][64][64] = 8192 floats
#define OFF_KT 8192            // [2][64][64] = 8192
#define OFF_SS 16384           // [64][65]    = 4160
#define OFF_V  0               // overlay: [2][16][256] = 8192 (inside QT region)
#define ATTN_SMEM_BYTES ((16384 + 4160) * 4)   // 82176 B

// swizzled index within a QT/KT chunk: element (e_loc, q)
__device__ __forceinline__ int qsw(int el, int q) {
    return el * 64 + ((((q) >> 2) ^ (el & 15)) << 2) + (q & 3);
}

__global__ __launch_bounds__(256, 2)
void attn_kernel(const float* __restrict__ Qg, const float* __restrict__ Kg,
                 const float* __restrict__ Vg, float* __restrict__ Ag)
{
    extern __shared__ float sm[];
    float* QT = sm + OFF_QT;
    float* KT = sm + OFF_KT;
    float* Ss = sm + OFF_SS;
    float* Vc = sm + OFF_V;

    const int tid = threadIdx.x;
    const int b   = blockIdx.x;
    const size_t base = (size_t)b * TT * EE;
    const float* qb = Qg + base;
    const float* kb = Kg + base;
    const float* vb = Vg + base;

    // loader mapping: column e_loc = tid&63, rows h*16..h*16+15
    const int el = tid & 63;
    const int h  = tid >> 6;

    // compute mapping (S-phase): tx = k-group (4 cols), ty = q-group (4 rows)
    const int tx = tid & 15;
    const int ty = tid >> 4;

    // ---- preload chunk 0 (Q,K transposed+swizzled) ----
    {
        const float* qsrc = qb + (h * 16) * EE + el;
        const float* ksrc = kb + (h * 16) * EE + el;
        float qs[16], ks[16];
        #pragma unroll
        for (int r = 0; r < 16; ++r) {
            qs[r] = qsrc[r * EE];
            ks[r] = ksrc[r * EE];
        }
        #pragma unroll
        for (int r = 0; r < 16; ++r) {
            const int q = h * 16 + r;
            QT[qsw(el, q)] = qs[r];
            KT[qsw(el, q)] = ks[r];
        }
    }

    // ---- S = Q @ K^T over 4 e-chunks ----
    uint64_t accS[4][2];
    #pragma unroll
    for (int i = 0; i < 4; ++i) { accS[i][0] = 0ull; accS[i][1] = 0ull; }

    int cur = 0;
    float qs[16], ks[16];
    for (int ec = 0; ec < NEC; ++ec) {
        __syncthreads();
        if (ec < NEC - 1) {   // issue LDG for next chunk (hidden under compute)
            const float* qsrc = qb + (h * 16) * EE + (ec + 1) * EC + el;
            const float* ksrc = kb + (h * 16) * EE + (ec + 1) * EC + el;
            #pragma unroll
            for (int r = 0; r < 16; ++r) {
                qs[r] = qsrc[r * EE];
                ks[r] = ksrc[r * EE];
            }
        }
        const float* Qb = QT + cur * 4096;
        const float* Kb = KT + cur * 4096;
        #pragma unroll 4
        for (int e = 0; e < EC; ++e) {
            const int sw = e & 15;
            float4 qv = *(const float4*)&Qb[e * 64 + ((ty ^ sw) << 2)];
            float4 kv = *(const float4*)&Kb[e * 64 + ((tx ^ sw) << 2)];
            const uint64_t* kp = (const uint64_t*)&kv;
            ffma2(accS[0][0], dupf(qv.x), kp[0]);
            ffma2(accS[0][1], dupf(qv.x), kp[1]);
            ffma2(accS[1][0], dupf(qv.y), kp[0]);
            ffma2(accS[1][1], dupf(qv.y), kp[1]);
            ffma2(accS[2][0], dupf(qv.z), kp[0]);
            ffma2(accS[2][1], dupf(qv.z), kp[1]);
            ffma2(accS[3][0], dupf(qv.w), kp[0]);
            ffma2(accS[3][1], dupf(qv.w), kp[1]);
        }
        if (ec < NEC - 1) {
            float* Qn = QT + (cur ^ 1) * 4096;
            float* Kn = KT + (cur ^ 1) * 4096;
            #pragma unroll
            for (int r = 0; r < 16; ++r) {
                const int q = h * 16 + r;
                Qn[qsw(el, q)] = qs[r];
                Kn[qsw(el, q)] = ks[r];
            }
            cur ^= 1;
        }
    }

    // store S
    #pragma unroll
    for (int i = 0; i < 4; ++i) {
        float s0, s1, s2, s3;
        unpack2(accS[i][0], s0, s1);
        unpack2(accS[i][1], s2, s3);
        float* sr = &Ss[(ty * 4 + i) * S_PITCH + tx * 4];
        sr[0] = s0; sr[1] = s1; sr[2] = s2; sr[3] = s3;
    }
    __syncthreads();   // S complete; QT/KT dead from here

    // ---- prefetch V chunk 0 (overlays QT region) under softmax ----
    const uint32_t vsm = smem_u32(Vc);
    #pragma unroll
    for (int j = 0; j < 4; ++j) {
        const int f4 = j * 256 + tid;
        CP_ASYNC16(vsm + f4 * 16, (const float4*)vb + f4);
    }
    CP_COMMIT();

    // ---- softmax: 8 warps x 8 rows ----
    const int warp = tid >> 5, lane = tid & 31;
    #pragma unroll
    for (int rr = 0; rr < 8; ++rr) {
        const int r = warp * 8 + rr;
        float v1 = Ss[r * S_PITCH + lane]      * SCALE;
        float v2 = Ss[r * S_PITCH + lane + 32] * SCALE;
        float m = fmaxf(v1, v2);
        #pragma unroll
        for (int o = 16; o > 0; o >>= 1)
            m = fmaxf(m, __shfl_xor_sync(0xffffffffu, m, o));
        float e1 = expf(v1 - m);
        float e2 = expf(v2 - m);
        float s = e1 + e2;
        #pragma unroll
        for (int o = 16; o > 0; o >>= 1)
            s += __shfl_xor_sync(0xffffffffu, s, o);
        float inv = 1.0f / s;
        Ss[r * S_PITCH + lane]      = e1 * inv;
        Ss[r * S_PITCH + lane + 32] = e2 * inv;
    }

    // ---- A = S @ V over 4 k-chunks (cp.async double buffer) ----
    uint64_t accA[4][4][2];   // [q][eb][pair]
    #pragma unroll
    for (int i = 0; i < 4; ++i)
        #pragma unroll
        for (int eb = 0; eb < 4; ++eb) { accA[i][eb][0] = 0ull; accA[i][eb][1] = 0ull; }

    for (int kc = 0; kc < NKC; ++kc) {
        if (kc < NKC - 1) {
            const uint32_t dst = vsm + (((kc + 1) & 1) * 4096) * 4;
            #pragma unroll
            for (int j = 0; j < 4; ++j) {
                const int f4 = j * 256 + tid;
                CP_ASYNC16(dst + f4 * 16, (const float4*)vb + (kc + 1) * 1024 + f4);
            }
            CP_COMMIT();
            CP_WAIT(1);
        } else {
            CP_WAIT(0);
        }
        __syncthreads();
        const float* Vb = Vc + (kc & 1) * 4096;
        #pragma unroll 2
        for (int kl = 0; kl < KC; ++kl) {
            const int kg = kc * KC + kl;
            float4 v0 = *(const float4*)&Vb[kl * 256 + tx * 4];
            float4 v1 = *(const float4*)&Vb[kl * 256 + 64 + tx * 4];
            float4 v2 = *(const float4*)&Vb[kl * 256 + 128 + tx * 4];
            float4 v3 = *(const float4*)&Vb[kl * 256 + 192 + tx * 4];
            uint64_t vp[4][2];
            { const uint64_t* u = (const uint64_t*)&v0; vp[0][0] = u[0]; vp[0][1] = u[1]; }
            { const uint64_t* u = (const uint64_t*)&v1; vp[1][0] = u[0]; vp[1][1] = u[1]; }
            { const uint64_t* u = (const uint64_t*)&v2; vp[2][0] = u[0]; vp[2][1] = u[1]; }
            { const uint64_t* u = (const uint64_t*)&v3; vp[3][0] = u[0]; vp[3][1] = u[1]; }
            #pragma unroll
            for (int i = 0; i < 4; ++i) {
                uint64_t sd = dupf(Ss[(ty * 4 + i) * S_PITCH + kg]);
                #pragma unroll
                for (int eb = 0; eb < 4; ++eb) {
                    ffma2(accA[i][eb][0], sd, vp[eb][0]);
                    ffma2(accA[i][eb][1], sd, vp[eb][1]);
                }
            }
        }
        __syncthreads();
    }

    // ---- epilogue: attn -> Ag, x = attn + q(global) -> g_x ----
    float* ab = Ag + base;
    float* xb = g_x + base;
    #pragma unroll
    for (int i = 0; i < 4; ++i) {
        const int qrow = ty * 4 + i;
        #pragma unroll
        for (int eb = 0; eb < 4; ++eb) {
            const int e0 = eb * 64 + tx * 4;
            float4 o;
            unpack2(accA[i][eb][0], o.x, o.y);
            unpack2(accA[i][eb][1], o.z, o.w);
            float4 q = *(const float4*)&qb[qrow * EE + e0];
            float4 x = make_float4(o.x + q.x, o.y + q.y, o.z + q.z, o.w + q.w);
            *(float4*)&ab[qrow * EE + e0] = o;
            *(float4*)&xb[qrow * EE + e0] = x;
        }
    }
}

// ------------------------------------------------------------------
// FF GEMM: partial[s][m][n] = g_x[m, s-range] @ W^T   (FFMA2 SIMT)
// 256 threads, BM=128 BN=128 BK=16, 8x8 tile, W stored DUPLICATED in
// smem (pairs), so the hot loop has zero dup-MOVs.
// grid (16, 2, SPLITK), 2 CTAs/SM.
// ------------------------------------------------------------------
#define FBM 128
#define FBN 128
#define FBK 16
#define XP 132                  // Xs row pitch (floats)
#define WBLK 20                 // words per n-block: 8 n dup'd (16) + 4 pad
#define WROW (16 * WBLK)        // 320 words per k-row
#define XS_WORDS (2 * FBK * XP)     // 4224
#define WD_WORDS (2 * FBK * WROW)   // 10240
#define FF_SMEM_BYTES ((XS_WORDS + WD_WORDS) * 4)   // 57856
#define NTILE (KSPL / FBK)      // 128

__global__ __launch_bounds__(256, 2)
void ff2_kernel(const float* __restrict__ Wg)
{
    extern __shared__ float fsm[];
    float* Xs = fsm;                  // [2][16][132]
    float* Wd = fsm + XS_WORDS;       // [2][16][320]

    const int tid = threadIdx.x;
    const int m0 = blockIdx.x * FBM;
    const int n0 = blockIdx.y * FBN;
    const size_t kbase = (size_t)blockIdx.z * KSPL;

    const int lrow = tid >> 2;          // 0..63
    const int lc   = (tid & 3) * 4;     // 0,4,8,12
    const float* xp0 = g_x + (size_t)(m0 + lrow) * FK + kbase + lc;
    const float* xp1 = g_x + (size_t)(m0 + 64 + lrow) * FK + kbase + lc;
    const float* wp0 = Wg  + (size_t)(n0 + lrow) * FK + kbase + lc;
    const float* wp1 = Wg  + (size_t)(n0 + 64 + lrow) * FK + kbase + lc;

    const int wa_off = WBLK * (lrow >> 3) + 2 * (lrow & 7);
    const int wb_off = WBLK * (8 + (lrow >> 3)) + 2 * (lrow & 7);

    const int tx = tid & 15;    // n block: cols tx*8..+7
    const int ty = tid >> 4;    // m rows ty*8..+7

    uint64_t acc[4][8];         // [m-pair][n]
    #pragma unroll
    for (int mp = 0; mp < 4; ++mp)
        #pragma unroll
        for (int n = 0; n < 8; ++n) acc[mp][n] = 0ull;

    float4 xA = *(const float4*)xp0;
    float4 xB = *(const float4*)xp1;
    float4 wA = *(const float4*)wp0;
    float4 wB = *(const float4*)wp1;

    for (int t = 0; t < NTILE; ++t) {
        const int buf = t & 1;
        float* Xb = Xs + buf * FBK * XP;
        float* Wb = Wd + buf * FBK * WROW;
        {
            const float* a0 = (const float*)&xA;
            const float* a1 = (const float*)&xB;
            const float* w0 = (const float*)&wA;
            const float* w1 = (const float*)&wB;
            #pragma unroll
            for (int j = 0; j < 4; ++j) {
                Xb[(lc + j) * XP + lrow]      = a0[j];
                Xb[(lc + j) * XP + lrow + 64] = a1[j];
                *(uint64_t*)&Wb[(lc + j) * WROW + wa_off] = dupf(w0[j]);
                *(uint64_t*)&Wb[(lc + j) * WROW + wb_off] = dupf(w1[j]);
            }
        }
        __syncthreads();

        if (t + 1 < NTILE) {
            const size_t kt = (size_t)(t + 1) * FBK;
            xA = *(const float4*)(xp0 + kt);
            xB = *(const float4*)(xp1 + kt);
            wA = *(const float4*)(wp0 + kt);
            wB = *(const float4*)(wp1 + kt);
        }

        #pragma unroll
        for (int k = 0; k < FBK; ++k) {
            const float* xr = Xb + k * XP + ty * 8;
            float4 a0 = *(const float4*)xr;
            float4 a1 = *(const float4*)(xr + 4);
            uint64_t ap[4];
            { const uint64_t* u = (const uint64_t*)&a0; ap[0] = u[0]; ap[1] = u[1]; }
            { const uint64_t* u = (const uint64_t*)&a1; ap[2] = u[0]; ap[3] = u[1]; }
            const float* wr = Wb + k * WROW + WBLK * tx;
            uint64_t bp[8];
            #pragma unroll
            for (int c = 0; c < 4; ++c) {
                float4 bv = *(const float4*)(wr + 4 * c);
                const uint64_t* u = (const uint64_t*)&bv;
                bp[2 * c]     = u[0];
                bp[2 * c + 1] = u[1];
            }
            #pragma unroll
            for (int mp = 0; mp < 4; ++mp)
                #pragma unroll
                for (int n = 0; n < 8; ++n)
                    ffma2(acc[mp][n], ap[mp], bp[n]);
        }
        __syncthreads();
    }

    #pragma unroll
    for (int mp = 0; mp < 4; ++mp) {
        float lo[8], hi[8];
        #pragma unroll
        for (int n = 0; n < 8; ++n) unpack2(acc[mp][n], lo[n], hi[n]);
        const int mlo = m0 + ty * 8 + mp * 2;
        float* p0 = g_partial + ((size_t)blockIdx.z * BATCH + mlo) * 256 + n0 + tx * 8;
        float* p1 = p0 + 256;
        *(float4*)p0       = make_float4(lo[0], lo[1], lo[2], lo[3]);
        *(float4*)(p0 + 4) = make_float4(lo[4], lo[5], lo[6], lo[7]);
        *(float4*)p1       = make_float4(hi[0], hi[1], hi[2], hi[3]);
        *(float4*)(p1 + 4) = make_float4(hi[4], hi[5], hi[6], hi[7]);
    }
}

// ------------------------------------------------------------------
// reduce: out = relu(sum_s partial + bias)
// ------------------------------------------------------------------
__global__ __launch_bounds__(256)
void reduce_kernel(const float* __restrict__ bias, float* __restrict__ out)
{
    const int g = blockIdx.x * 256 + threadIdx.x;   // float4 index
    const int m = g >> 6;
    const int nc = g & 63;
    float4 acc = ((const float4*)bias)[nc];
    #pragma unroll
    for (int ks = 0; ks < SPLITK; ++ks) {
        float4 p = ((const float4*)g_partial)[((size_t)ks * BATCH + m) * 64 + nc];
        acc.x += p.x; acc.y += p.y; acc.z += p.z; acc.w += p.w;
    }
    acc.x = fmaxf(acc.x, 0.0f); acc.y = fmaxf(acc.y, 0.0f);
    acc.z = fmaxf(acc.z, 0.0f); acc.w = fmaxf(acc.w, 0.0f);
    ((float4*)out)[(size_t)m * 64 + nc] = acc;
}

// ------------------------------------------------------------------
// launch
// ------------------------------------------------------------------
extern "C" void kernel_launch(void* const* d_in, const int* in_sizes, int n_in,
                              void* d_out, int out_size)
{
    const float* value = (const float*)d_in[0];
    const float* key_  = (const float*)d_in[1];
    const float* query = (const float*)d_in[2];
    const float* W_ff  = (const float*)d_in[4];
    const float* b_ff  = (const float*)d_in[5];

    float* out  = (float*)d_out;                 // [2048, 256]
    float* attn = out + (size_t)BATCH * 256;     // [2048, 64, 256]

    cudaFuncSetAttribute(attn_kernel,
                         cudaFuncAttributeMaxDynamicSharedMemorySize, ATTN_SMEM_BYTES);
    cudaFuncSetAttribute(ff2_kernel,
                         cudaFuncAttributeMaxDynamicSharedMemorySize, FF_SMEM_BYTES);

    attn_kernel<<<BATCH, 256, ATTN_SMEM_BYTES>>>(query, key_, value, attn);
    ff2_kernel<<<dim3(16, 2, SPLITK), 256, FF_SMEM_BYTES>>>(W_ff);
    reduce_kernel<<<512, 256>>>(b_ff, out);
}

// round 9
// speedup vs baseline: 1.8184x; 1.1289x over previous
#include <cuda_runtime.h>
#include <cstdint>
#include <math.h>

#define BATCH 2048
#define TT 64
#define EE 256
#define SCALE 0.125f
#define FK  16384
#define SPLITK 8
#define KSPL (FK / SPLITK)          // 2048

// ------------------------------------------------------------------
// scratch (static __device__ — no allocations allowed)
// ------------------------------------------------------------------
__device__ float g_x[BATCH * TT * EE];              // attn + query (134MB)
__device__ float g_partial[SPLITK * BATCH * 256];   // 16MB

// ------------------------------------------------------------------
// packed f32x2 helpers (FFMA2 — only reachable via PTX fma.rn.f32x2)
// ------------------------------------------------------------------
__device__ __forceinline__ void ffma2(uint64_t& d, uint64_t a, uint64_t b) {
    asm("fma.rn.f32x2 %0, %1, %2, %0;" : "+l"(d) : "l"(a), "l"(b));
}
__device__ __forceinline__ uint64_t dupf(float x) {
    uint64_t d; asm("mov.b64 %0, {%1, %1};" : "=l"(d) : "f"(x)); return d;
}
__device__ __forceinline__ void unpack2(uint64_t d, float& lo, float& hi) {
    asm("mov.b64 {%0, %1}, %2;" : "=f"(lo), "=f"(hi) : "l"(d));
}
__device__ __forceinline__ uint32_t smem_u32(const void* p) {
    uint32_t a;
    asm("{ .reg .u64 t; cvta.to.shared.u64 t, %1; cvt.u32.u64 %0, t; }" : "=r"(a) : "l"(p));
    return a;
}
#define CP_ASYNC16(dst, src) \
    asm volatile("cp.async.cg.shared.global [%0], [%1], 16;" :: "r"(dst), "l"(src) : "memory")
#define CP_COMMIT() \
    asm volatile("cp.async.commit_group;" ::: "memory")
#define CP_WAIT(n) \
    asm volatile("cp.async.wait_group %0;" :: "n"(n) : "memory")

// ------------------------------------------------------------------
// attention kernel: 256 threads, 2 CTAs/SM. (unchanged from R8)
// ------------------------------------------------------------------
#define EC 64
#define NEC 4
#define KC 16
#define NKC 4
#define S_PITCH 65

#define OFF_QT 0
#define OFF_KT 8192
#define OFF_SS 16384
#define OFF_V  0
#define ATTN_SMEM_BYTES ((16384 + 4160) * 4)

__device__ __forceinline__ int qsw(int el, int q) {
    return el * 64 + ((((q) >> 2) ^ (el & 15)) << 2) + (q & 3);
}

__global__ __launch_bounds__(256, 2)
void attn_kernel(const float* __restrict__ Qg, const float* __restrict__ Kg,
                 const float* __restrict__ Vg, float* __restrict__ Ag)
{
    extern __shared__ float sm[];
    float* QT = sm + OFF_QT;
    float* KT = sm + OFF_KT;
    float* Ss = sm + OFF_SS;
    float* Vc = sm + OFF_V;

    const int tid = threadIdx.x;
    const int b   = blockIdx.x;
    const size_t base = (size_t)b * TT * EE;
    const float* qb = Qg + base;
    const float* kb = Kg + base;
    const float* vb = Vg + base;

    const int el = tid & 63;
    const int h  = tid >> 6;
    const int tx = tid & 15;
    const int ty = tid >> 4;

    {
        const float* qsrc = qb + (h * 16) * EE + el;
        const float* ksrc = kb + (h * 16) * EE + el;
        float qs[16], ks[16];
        #pragma unroll
        for (int r = 0; r < 16; ++r) {
            qs[r] = qsrc[r * EE];
            ks[r] = ksrc[r * EE];
        }
        #pragma unroll
        for (int r = 0; r < 16; ++r) {
            const int q = h * 16 + r;
            QT[qsw(el, q)] = qs[r];
            KT[qsw(el, q)] = ks[r];
        }
    }

    uint64_t accS[4][2];
    #pragma unroll
    for (int i = 0; i < 4; ++i) { accS[i][0] = 0ull; accS[i][1] = 0ull; }

    int cur = 0;
    float qs[16], ks[16];
    for (int ec = 0; ec < NEC; ++ec) {
        __syncthreads();
        if (ec < NEC - 1) {
            const float* qsrc = qb + (h * 16) * EE + (ec + 1) * EC + el;
            const float* ksrc = kb + (h * 16) * EE + (ec + 1) * EC + el;
            #pragma unroll
            for (int r = 0; r < 16; ++r) {
                qs[r] = qsrc[r * EE];
                ks[r] = ksrc[r * EE];
            }
        }
        const float* Qb = QT + cur * 4096;
        const float* Kb = KT + cur * 4096;
        #pragma unroll 4
        for (int e = 0; e < EC; ++e) {
            const int sw = e & 15;
            float4 qv = *(const float4*)&Qb[e * 64 + ((ty ^ sw) << 2)];
            float4 kv = *(const float4*)&Kb[e * 64 + ((tx ^ sw) << 2)];
            const uint64_t* kp = (const uint64_t*)&kv;
            ffma2(accS[0][0], dupf(qv.x), kp[0]);
            ffma2(accS[0][1], dupf(qv.x), kp[1]);
            ffma2(accS[1][0], dupf(qv.y), kp[0]);
            ffma2(accS[1][1], dupf(qv.y), kp[1]);
            ffma2(accS[2][0], dupf(qv.z), kp[0]);
            ffma2(accS[2][1], dupf(qv.z), kp[1]);
            ffma2(accS[3][0], dupf(qv.w), kp[0]);
            ffma2(accS[3][1], dupf(qv.w), kp[1]);
        }
        if (ec < NEC - 1) {
            float* Qn = QT + (cur ^ 1) * 4096;
            float* Kn = KT + (cur ^ 1) * 4096;
            #pragma unroll
            for (int r = 0; r < 16; ++r) {
                const int q = h * 16 + r;
                Qn[qsw(el, q)] = qs[r];
                Kn[qsw(el, q)] = ks[r];
            }
            cur ^= 1;
        }
    }

    #pragma unroll
    for (int i = 0; i < 4; ++i) {
        float s0, s1, s2, s3;
        unpack2(accS[i][0], s0, s1);
        unpack2(accS[i][1], s2, s3);
        float* sr = &Ss[(ty * 4 + i) * S_PITCH + tx * 4];
        sr[0] = s0; sr[1] = s1; sr[2] = s2; sr[3] = s3;
    }
    __syncthreads();

    const uint32_t vsm = smem_u32(Vc);
    #pragma unroll
    for (int j = 0; j < 4; ++j) {
        const int f4 = j * 256 + tid;
        CP_ASYNC16(vsm + f4 * 16, (const float4*)vb + f4);
    }
    CP_COMMIT();

    const int warp = tid >> 5, lane = tid & 31;
    #pragma unroll
    for (int rr = 0; rr < 8; ++rr) {
        const int r = warp * 8 + rr;
        float v1 = Ss[r * S_PITCH + lane]      * SCALE;
        float v2 = Ss[r * S_PITCH + lane + 32] * SCALE;
        float m = fmaxf(v1, v2);
        #pragma unroll
        for (int o = 16; o > 0; o >>= 1)
            m = fmaxf(m, __shfl_xor_sync(0xffffffffu, m, o));
        float e1 = expf(v1 - m);
        float e2 = expf(v2 - m);
        float s = e1 + e2;
        #pragma unroll
        for (int o = 16; o > 0; o >>= 1)
            s += __shfl_xor_sync(0xffffffffu, s, o);
        float inv = 1.0f / s;
        Ss[r * S_PITCH + lane]      = e1 * inv;
        Ss[r * S_PITCH + lane + 32] = e2 * inv;
    }

    uint64_t accA[4][4][2];
    #pragma unroll
    for (int i = 0; i < 4; ++i)
        #pragma unroll
        for (int eb = 0; eb < 4; ++eb) { accA[i][eb][0] = 0ull; accA[i][eb][1] = 0ull; }

    for (int kc = 0; kc < NKC; ++kc) {
        if (kc < NKC - 1) {
            const uint32_t dst = vsm + (((kc + 1) & 1) * 4096) * 4;
            #pragma unroll
            for (int j = 0; j < 4; ++j) {
                const int f4 = j * 256 + tid;
                CP_ASYNC16(dst + f4 * 16, (const float4*)vb + (kc + 1) * 1024 + f4);
            }
            CP_COMMIT();
            CP_WAIT(1);
        } else {
            CP_WAIT(0);
        }
        __syncthreads();
        const float* Vb = Vc + (kc & 1) * 4096;
        #pragma unroll 2
        for (int kl = 0; kl < KC; ++kl) {
            const int kg = kc * KC + kl;
            float4 v0 = *(const float4*)&Vb[kl * 256 + tx * 4];
            float4 v1 = *(const float4*)&Vb[kl * 256 + 64 + tx * 4];
            float4 v2 = *(const float4*)&Vb[kl * 256 + 128 + tx * 4];
            float4 v3 = *(const float4*)&Vb[kl * 256 + 192 + tx * 4];
            uint64_t vp[4][2];
            { const uint64_t* u = (const uint64_t*)&v0; vp[0][0] = u[0]; vp[0][1] = u[1]; }
            { const uint64_t* u = (const uint64_t*)&v1; vp[1][0] = u[0]; vp[1][1] = u[1]; }
            { const uint64_t* u = (const uint64_t*)&v2; vp[2][0] = u[0]; vp[2][1] = u[1]; }
            { const uint64_t* u = (const uint64_t*)&v3; vp[3][0] = u[0]; vp[3][1] = u[1]; }
            #pragma unroll
            for (int i = 0; i < 4; ++i) {
                uint64_t sd = dupf(Ss[(ty * 4 + i) * S_PITCH + kg]);
                #pragma unroll
                for (int eb = 0; eb < 4; ++eb) {
                    ffma2(accA[i][eb][0], sd, vp[eb][0]);
                    ffma2(accA[i][eb][1], sd, vp[eb][1]);
                }
            }
        }
        __syncthreads();
    }

    float* ab = Ag + base;
    float* xb = g_x + base;
    #pragma unroll
    for (int i = 0; i < 4; ++i) {
        const int qrow = ty * 4 + i;
        #pragma unroll
        for (int eb = 0; eb < 4; ++eb) {
            const int e0 = eb * 64 + tx * 4;
            float4 o;
            unpack2(accA[i][eb][0], o.x, o.y);
            unpack2(accA[i][eb][1], o.z, o.w);
            float4 q = *(const float4*)&qb[qrow * EE + e0];
            float4 x = make_float4(o.x + q.x, o.y + q.y, o.z + q.z, o.w + q.w);
            *(float4*)&ab[qrow * EE + e0] = o;
            *(float4*)&xb[qrow * EE + e0] = x;
        }
    }
}

// ------------------------------------------------------------------
// FF GEMM: partial[s][m][n] = g_x[m, s-range] @ W^T   (FFMA2 SIMT)
// 256 threads, BM=128 BN=128 BK=16, 8m x 8n tile.
// Accumulators packed over n (W rows are n-contiguous in smem -> b pairs
// load naturally packed); a(m) scalars dup'd via ALU MOVs (hidden under FMA).
// grid (16, 2, SPLITK), 2 CTAs/SM.
// ------------------------------------------------------------------
#define FBM 128
#define FBN 128
#define FBK 16
#define XP 132                       // row pitch (floats) for Xs and Ws
#define TILE_WORDS (FBK * XP)        // 2112
#define FF_SMEM_BYTES (4 * TILE_WORDS * 4)   // 2 bufs x (Xs+Ws) = 33792 B
#define NTILE (KSPL / FBK)           // 128

__global__ __launch_bounds__(256, 2)
void ff2_kernel(const float* __restrict__ Wg)
{
    extern __shared__ float fsm[];
    float* Xs = fsm;                         // [2][16][132]
    float* Ws = fsm + 2 * TILE_WORDS;        // [2][16][132]

    const int tid = threadIdx.x;
    const int m0 = blockIdx.x * FBM;
    const int n0 = blockIdx.y * FBN;
    const size_t kbase = (size_t)blockIdx.z * KSPL;

    const int lrow = tid >> 2;          // 0..63
    const int lc   = (tid & 3) * 4;     // 0,4,8,12
    const float* xp0 = g_x + (size_t)(m0 + lrow) * FK + kbase + lc;
    const float* xp1 = g_x + (size_t)(m0 + 64 + lrow) * FK + kbase + lc;
    const float* wp0 = Wg  + (size_t)(n0 + lrow) * FK + kbase + lc;
    const float* wp1 = Wg  + (size_t)(n0 + 64 + lrow) * FK + kbase + lc;

    const int tx = tid & 15;    // n block: cols tx*8..+7
    const int ty = tid >> 4;    // m rows ty*8..+7  (lanes 0-15 share ty -> LDS broadcast)

    uint64_t acc[8][4];         // [m][n-pair]
    #pragma unroll
    for (int m = 0; m < 8; ++m)
        #pragma unroll
        for (int p = 0; p < 4; ++p) acc[m][p] = 0ull;

    float4 xA = *(const float4*)xp0;
    float4 xB = *(const float4*)xp1;
    float4 wA = *(const float4*)wp0;
    float4 wB = *(const float4*)wp1;

    for (int t = 0; t < NTILE; ++t) {
        const int buf = t & 1;
        float* Xb = Xs + buf * TILE_WORDS;
        float* Wb = Ws + buf * TILE_WORDS;
        {
            const float* a0 = (const float*)&xA;
            const float* a1 = (const float*)&xB;
            const float* w0 = (const float*)&wA;
            const float* w1 = (const float*)&wB;
            #pragma unroll
            for (int j = 0; j < 4; ++j) {
                Xb[(lc + j) * XP + lrow]      = a0[j];
                Xb[(lc + j) * XP + lrow + 64] = a1[j];
                Wb[(lc + j) * XP + lrow]      = w0[j];
                Wb[(lc + j) * XP + lrow + 64] = w1[j];
            }
        }
        __syncthreads();

        if (t + 1 < NTILE) {
            const size_t kt = (size_t)(t + 1) * FBK;
            xA = *(const float4*)(xp0 + kt);
            xB = *(const float4*)(xp1 + kt);
            wA = *(const float4*)(wp0 + kt);
            wB = *(const float4*)(wp1 + kt);
        }

        #pragma unroll
        for (int k = 0; k < FBK; ++k) {
            const float* xr = Xb + k * XP + ty * 8;
            float4 a0 = *(const float4*)xr;          // broadcast across 16 lanes
            float4 a1 = *(const float4*)(xr + 4);
            const float* wr = Wb + k * XP + tx * 8;
            float4 b0 = *(const float4*)wr;          // naturally packed n-pairs
            float4 b1 = *(const float4*)(wr + 4);
            uint64_t bp[4];
            { const uint64_t* u = (const uint64_t*)&b0; bp[0] = u[0]; bp[1] = u[1]; }
            { const uint64_t* u = (const uint64_t*)&b1; bp[2] = u[0]; bp[3] = u[1]; }
            const float aa[8] = {a0.x, a0.y, a0.z, a0.w, a1.x, a1.y, a1.z, a1.w};
            #pragma unroll
            for (int m = 0; m < 8; ++m) {
                uint64_t ad = dupf(aa[m]);
                #pragma unroll
                for (int p = 0; p < 4; ++p) ffma2(acc[m][p], ad, bp[p]);
            }
        }
        __syncthreads();
    }

    // epilogue: unpack (packed over n -> consecutive cols) and store partials
    #pragma unroll
    for (int m = 0; m < 8; ++m) {
        float c[8];
        #pragma unroll
        for (int p = 0; p < 4; ++p) unpack2(acc[m][p], c[2 * p], c[2 * p + 1]);
        float* pr = g_partial + ((size_t)blockIdx.z * BATCH + m0 + ty * 8 + m) * 256
                    + n0 + tx * 8;
        *(float4*)pr       = make_float4(c[0], c[1], c[2], c[3]);
        *(float4*)(pr + 4) = make_float4(c[4], c[5], c[6], c[7]);
    }
}

// ------------------------------------------------------------------
// reduce: out = relu(sum_s partial + bias)
// ------------------------------------------------------------------
__global__ __launch_bounds__(256)
void reduce_kernel(const float* __restrict__ bias, float* __restrict__ out)
{
    const int g = blockIdx.x * 256 + threadIdx.x;   // float4 index
    const int m = g >> 6;
    const int nc = g & 63;
    float4 acc = ((const float4*)bias)[nc];
    #pragma unroll
    for (int ks = 0; ks < SPLITK; ++ks) {
        float4 p = ((const float4*)g_partial)[((size_t)ks * BATCH + m) * 64 + nc];
        acc.x += p.x; acc.y += p.y; acc.z += p.z; acc.w += p.w;
    }
    acc.x = fmaxf(acc.x, 0.0f); acc.y = fmaxf(acc.y, 0.0f);
    acc.z = fmaxf(acc.z, 0.0f); acc.w = fmaxf(acc.w, 0.0f);
    ((float4*)out)[(size_t)m * 64 + nc] = acc;
}

// ------------------------------------------------------------------
// launch
// ------------------------------------------------------------------
extern "C" void kernel_launch(void* const* d_in, const int* in_sizes, int n_in,
                              void* d_out, int out_size)
{
    const float* value = (const float*)d_in[0];
    const float* key_  = (const float*)d_in[1];
    const float* query = (const float*)d_in[2];
    const float* W_ff  = (const float*)d_in[4];
    const float* b_ff  = (const float*)d_in[5];

    float* out  = (float*)d_out;                 // [2048, 256]
    float* attn = out + (size_t)BATCH * 256;     // [2048, 64, 256]

    cudaFuncSetAttribute(attn_kernel,
                         cudaFuncAttributeMaxDynamicSharedMemorySize, ATTN_SMEM_BYTES);
    cudaFuncSetAttribute(ff2_kernel,
                         cudaFuncAttributeMaxDynamicSharedMemorySize, FF_SMEM_BYTES);

    attn_kernel<<<BATCH, 256, ATTN_SMEM_BYTES>>>(query, key_, value, attn);
    ff2_kernel<<<dim3(16, 2, SPLITK), 256, FF_SMEM_BYTES>>>(W_ff);
    reduce_kernel<<<512, 256>>>(b_ff, out);
}

// round 10
// speedup vs baseline: 2.0358x; 1.1196x over previous
#include <cuda_runtime.h>
#include <cstdint>
#include <math.h>

#define BATCH 2048
#define TT 64
#define EE 256
#define SCALE 0.125f
#define FK  16384
#define SPLITK 9            // uneven: 8 x 1824 + 1 x 1792

// ------------------------------------------------------------------
// scratch (static __device__ — no allocations allowed)
// ------------------------------------------------------------------
__device__ float g_x[BATCH * TT * EE];              // attn + query (134MB)
__device__ float g_partial[SPLITK * BATCH * 256];   // 18.9MB

// ------------------------------------------------------------------
// packed f32x2 helpers (FFMA2 — only reachable via PTX fma.rn.f32x2)
// ------------------------------------------------------------------
__device__ __forceinline__ void ffma2(uint64_t& d, uint64_t a, uint64_t b) {
    asm("fma.rn.f32x2 %0, %1, %2, %0;" : "+l"(d) : "l"(a), "l"(b));
}
__device__ __forceinline__ uint64_t dupf(float x) {
    uint64_t d; asm("mov.b64 %0, {%1, %1};" : "=l"(d) : "f"(x)); return d;
}
__device__ __forceinline__ void unpack2(uint64_t d, float& lo, float& hi) {
    asm("mov.b64 {%0, %1}, %2;" : "=f"(lo), "=f"(hi) : "l"(d));
}
__device__ __forceinline__ uint32_t smem_u32(const void* p) {
    uint32_t a;
    asm("{ .reg .u64 t; cvta.to.shared.u64 t, %1; cvt.u32.u64 %0, t; }" : "=r"(a) : "l"(p));
    return a;
}
#define CP_ASYNC16(dst, src) \
    asm volatile("cp.async.cg.shared.global [%0], [%1], 16;" :: "r"(dst), "l"(src) : "memory")
#define CP_COMMIT() \
    asm volatile("cp.async.commit_group;" ::: "memory")
#define CP_WAIT(n) \
    asm volatile("cp.async.wait_group %0;" :: "n"(n) : "memory")

// ------------------------------------------------------------------
// attention kernel: 256 threads, 2 CTAs/SM.
// ------------------------------------------------------------------
#define EC 64
#define NEC 4
#define KC 16
#define NKC 4
#define S_PITCH 65

#define OFF_QT 0
#define OFF_KT 8192
#define OFF_SS 16384
#define OFF_V  0
#define ATTN_SMEM_BYTES ((16384 + 4160) * 4)

__device__ __forceinline__ int qsw(int el, int q) {
    return el * 64 + ((((q) >> 2) ^ (el & 15)) << 2) + (q & 3);
}

__global__ __launch_bounds__(256, 2)
void attn_kernel(const float* __restrict__ Qg, const float* __restrict__ Kg,
                 const float* __restrict__ Vg, float* __restrict__ Ag)
{
    extern __shared__ float sm[];
    float* QT = sm + OFF_QT;
    float* KT = sm + OFF_KT;
    float* Ss = sm + OFF_SS;
    float* Vc = sm + OFF_V;

    const int tid = threadIdx.x;
    const int b   = blockIdx.x;
    const size_t base = (size_t)b * TT * EE;
    const float* qb = Qg + base;
    const float* kb = Kg + base;
    const float* vb = Vg + base;

    const int el = tid & 63;
    const int h  = tid >> 6;
    const int tx = tid & 15;
    const int ty = tid >> 4;

    {
        const float* qsrc = qb + (h * 16) * EE + el;
        const float* ksrc = kb + (h * 16) * EE + el;
        float qs[16], ks[16];
        #pragma unroll
        for (int r = 0; r < 16; ++r) {
            qs[r] = qsrc[r * EE];
            ks[r] = ksrc[r * EE];
        }
        #pragma unroll
        for (int r = 0; r < 16; ++r) {
            const int q = h * 16 + r;
            QT[qsw(el, q)] = qs[r];
            KT[qsw(el, q)] = ks[r];
        }
    }

    uint64_t accS[4][2];
    #pragma unroll
    for (int i = 0; i < 4; ++i) { accS[i][0] = 0ull; accS[i][1] = 0ull; }

    int cur = 0;
    float qs[16], ks[16];
    for (int ec = 0; ec < NEC; ++ec) {
        __syncthreads();
        if (ec < NEC - 1) {
            const float* qsrc = qb + (h * 16) * EE + (ec + 1) * EC + el;
            const float* ksrc = kb + (h * 16) * EE + (ec + 1) * EC + el;
            #pragma unroll
            for (int r = 0; r < 16; ++r) {
                qs[r] = qsrc[r * EE];
                ks[r] = ksrc[r * EE];
            }
        }
        const float* Qb = QT + cur * 4096;
        const float* Kb = KT + cur * 4096;
        #pragma unroll 16
        for (int e = 0; e < EC; ++e) {      // unroll 16: swizzle offsets fold to immediates
            const int sw = e & 15;
            float4 qv = *(const float4*)&Qb[e * 64 + ((ty ^ sw) << 2)];
            float4 kv = *(const float4*)&Kb[e * 64 + ((tx ^ sw) << 2)];
            const uint64_t* kp = (const uint64_t*)&kv;
            ffma2(accS[0][0], dupf(qv.x), kp[0]);
            ffma2(accS[0][1], dupf(qv.x), kp[1]);
            ffma2(accS[1][0], dupf(qv.y), kp[0]);
            ffma2(accS[1][1], dupf(qv.y), kp[1]);
            ffma2(accS[2][0], dupf(qv.z), kp[0]);
            ffma2(accS[2][1], dupf(qv.z), kp[1]);
            ffma2(accS[3][0], dupf(qv.w), kp[0]);
            ffma2(accS[3][1], dupf(qv.w), kp[1]);
        }
        if (ec < NEC - 1) {
            float* Qn = QT + (cur ^ 1) * 4096;
            float* Kn = KT + (cur ^ 1) * 4096;
            #pragma unroll
            for (int r = 0; r < 16; ++r) {
                const int q = h * 16 + r;
                Qn[qsw(el, q)] = qs[r];
                Kn[qsw(el, q)] = ks[r];
            }
            cur ^= 1;
        }
    }

    #pragma unroll
    for (int i = 0; i < 4; ++i) {
        float s0, s1, s2, s3;
        unpack2(accS[i][0], s0, s1);
        unpack2(accS[i][1], s2, s3);
        float* sr = &Ss[(ty * 4 + i) * S_PITCH + tx * 4];
        sr[0] = s0; sr[1] = s1; sr[2] = s2; sr[3] = s3;
    }
    __syncthreads();

    const uint32_t vsm = smem_u32(Vc);
    #pragma unroll
    for (int j = 0; j < 4; ++j) {
        const int f4 = j * 256 + tid;
        CP_ASYNC16(vsm + f4 * 16, (const float4*)vb + f4);
    }
    CP_COMMIT();

    const int warp = tid >> 5, lane = tid & 31;
    #pragma unroll
    for (int rr = 0; rr < 8; ++rr) {
        const int r = warp * 8 + rr;
        float v1 = Ss[r * S_PITCH + lane]      * SCALE;
        float v2 = Ss[r * S_PITCH + lane + 32] * SCALE;
        float m = fmaxf(v1, v2);
        #pragma unroll
        for (int o = 16; o > 0; o >>= 1)
            m = fmaxf(m, __shfl_xor_sync(0xffffffffu, m, o));
        float e1 = expf(v1 - m);
        float e2 = expf(v2 - m);
        float s = e1 + e2;
        #pragma unroll
        for (int o = 16; o > 0; o >>= 1)
            s += __shfl_xor_sync(0xffffffffu, s, o);
        float inv = 1.0f / s;
        Ss[r * S_PITCH + lane]      = e1 * inv;
        Ss[r * S_PITCH + lane + 32] = e2 * inv;
    }

    uint64_t accA[4][4][2];
    #pragma unroll
    for (int i = 0; i < 4; ++i)
        #pragma unroll
        for (int eb = 0; eb < 4; ++eb) { accA[i][eb][0] = 0ull; accA[i][eb][1] = 0ull; }

    for (int kc = 0; kc < NKC; ++kc) {
        if (kc < NKC - 1) {
            const uint32_t dst = vsm + (((kc + 1) & 1) * 4096) * 4;
            #pragma unroll
            for (int j = 0; j < 4; ++j) {
                const int f4 = j * 256 + tid;
                CP_ASYNC16(dst + f4 * 16, (const float4*)vb + (kc + 1) * 1024 + f4);
            }
            CP_COMMIT();
            CP_WAIT(1);
        } else {
            CP_WAIT(0);
        }
        __syncthreads();
        const float* Vb = Vc + (kc & 1) * 4096;
        #pragma unroll 2
        for (int kl = 0; kl < KC; ++kl) {
            const int kg = kc * KC + kl;
            float4 v0 = *(const float4*)&Vb[kl * 256 + tx * 4];
            float4 v1 = *(const float4*)&Vb[kl * 256 + 64 + tx * 4];
            float4 v2 = *(const float4*)&Vb[kl * 256 + 128 + tx * 4];
            float4 v3 = *(const float4*)&Vb[kl * 256 + 192 + tx * 4];
            uint64_t vp[4][2];
            { const uint64_t* u = (const uint64_t*)&v0; vp[0][0] = u[0]; vp[0][1] = u[1]; }
            { const uint64_t* u = (const uint64_t*)&v1; vp[1][0] = u[0]; vp[1][1] = u[1]; }
            { const uint64_t* u = (const uint64_t*)&v2; vp[2][0] = u[0]; vp[2][1] = u[1]; }
            { const uint64_t* u = (const uint64_t*)&v3; vp[3][0] = u[0]; vp[3][1] = u[1]; }
            #pragma unroll
            for (int i = 0; i < 4; ++i) {
                uint64_t sd = dupf(Ss[(ty * 4 + i) * S_PITCH + kg]);
                #pragma unroll
                for (int eb = 0; eb < 4; ++eb) {
                    ffma2(accA[i][eb][0], sd, vp[eb][0]);
                    ffma2(accA[i][eb][1], sd, vp[eb][1]);
                }
            }
        }
        __syncthreads();
    }

    float* ab = Ag + base;
    float* xb = g_x + base;
    #pragma unroll
    for (int i = 0; i < 4; ++i) {
        const int qrow = ty * 4 + i;
        #pragma unroll
        for (int eb = 0; eb < 4; ++eb) {
            const int e0 = eb * 64 + tx * 4;
            float4 o;
            unpack2(accA[i][eb][0], o.x, o.y);
            unpack2(accA[i][eb][1], o.z, o.w);
            float4 q = *(const float4*)&qb[qrow * EE + e0];
            float4 x = make_float4(o.x + q.x, o.y + q.y, o.z + q.z, o.w + q.w);
            *(float4*)&ab[qrow * EE + e0] = o;
            *(float4*)&xb[qrow * EE + e0] = x;
        }
    }
}

// ------------------------------------------------------------------
// FF GEMM: partial[s][m][n] = g_x[m, s-range] @ W^T   (FFMA2 SIMT)
// 256 threads, BM=128 BN=128 BK=32, 8m x 8n tile, acc packed over n.
// grid (16, 2, 9): 288 CTAs (97% of 296 slots), uneven k-splits.
// ------------------------------------------------------------------
#define FBM 128
#define FBN 128
#define FBK 32
#define XP 132                       // row pitch (floats)
#define TILE_WORDS (FBK * XP)        // 4224
#define FF_SMEM_BYTES (4 * TILE_WORDS * 4)   // 2 bufs x (Xs+Ws) = 67584 B
#define KTPS 57                      // k-tiles (of 32) per split, splits 0..7; split 8: 56

__global__ __launch_bounds__(256, 2)
void ff2_kernel(const float* __restrict__ Wg)
{
    extern __shared__ float fsm[];
    float* Xs = fsm;                         // [2][32][132]
    float* Ws = fsm + 2 * TILE_WORDS;        // [2][32][132]

    const int tid = threadIdx.x;
    const int m0 = blockIdx.x * FBM;
    const int n0 = blockIdx.y * FBN;
    const int z  = blockIdx.z;
    const size_t kbase = (size_t)z * (KTPS * FBK);      // z*1824
    const int ntile = (z == SPLITK - 1) ? 56 : KTPS;

    const int lrow = tid >> 2;          // 0..63
    const int lc   = (tid & 3) * 4;     // 0,4,8,12
    const float* xp0 = g_x + (size_t)(m0 + lrow) * FK + kbase + lc;
    const float* xp1 = g_x + (size_t)(m0 + 64 + lrow) * FK + kbase + lc;
    const float* wp0 = Wg  + (size_t)(n0 + lrow) * FK + kbase + lc;
    const float* wp1 = Wg  + (size_t)(n0 + 64 + lrow) * FK + kbase + lc;

    const int tx = tid & 15;    // n block: cols tx*8..+7
    const int ty = tid >> 4;    // m rows ty*8..+7 (lanes 0-15 share ty -> LDS broadcast)

    uint64_t acc[8][4];         // [m][n-pair]
    #pragma unroll
    for (int m = 0; m < 8; ++m)
        #pragma unroll
        for (int p = 0; p < 4; ++p) acc[m][p] = 0ull;

    // prologue: stage tile 0 (two k-halves: +0 and +16)
    float4 xA0 = *(const float4*)xp0,        xA1 = *(const float4*)(xp0 + 16);
    float4 xB0 = *(const float4*)xp1,        xB1 = *(const float4*)(xp1 + 16);
    float4 wA0 = *(const float4*)wp0,        wA1 = *(const float4*)(wp0 + 16);
    float4 wB0 = *(const float4*)wp1,        wB1 = *(const float4*)(wp1 + 16);

    for (int t = 0; t < ntile; ++t) {
        const int buf = t & 1;
        float* Xb = Xs + buf * TILE_WORDS;
        float* Wb = Ws + buf * TILE_WORDS;
        {
            const float* a0 = (const float*)&xA0; const float* a1 = (const float*)&xA1;
            const float* b0 = (const float*)&xB0; const float* b1 = (const float*)&xB1;
            const float* c0 = (const float*)&wA0; const float* c1 = (const float*)&wA1;
            const float* d0 = (const float*)&wB0; const float* d1 = (const float*)&wB1;
            #pragma unroll
            for (int j = 0; j < 4; ++j) {
                Xb[(lc + j) * XP + lrow]           = a0[j];
                Xb[(lc + 16 + j) * XP + lrow]      = a1[j];
                Xb[(lc + j) * XP + lrow + 64]      = b0[j];
                Xb[(lc + 16 + j) * XP + lrow + 64] = b1[j];
                Wb[(lc + j) * XP + lrow]           = c0[j];
                Wb[(lc + 16 + j) * XP + lrow]      = c1[j];
                Wb[(lc + j) * XP + lrow + 64]      = d0[j];
                Wb[(lc + 16 + j) * XP + lrow + 64] = d1[j];
            }
        }
        __syncthreads();

        if (t + 1 < ntile) {    // prefetch next tile (~512 cyc of compute to hide)
            const size_t kt = (size_t)(t + 1) * FBK;
            xA0 = *(const float4*)(xp0 + kt);  xA1 = *(const float4*)(xp0 + kt + 16);
            xB0 = *(const float4*)(xp1 + kt);  xB1 = *(const float4*)(xp1 + kt + 16);
            wA0 = *(const float4*)(wp0 + kt);  wA1 = *(const float4*)(wp0 + kt + 16);
            wB0 = *(const float4*)(wp1 + kt);  wB1 = *(const float4*)(wp1 + kt + 16);
        }

        #pragma unroll
        for (int k = 0; k < FBK; ++k) {
            const float* xr = Xb + k * XP + ty * 8;
            float4 a0 = *(const float4*)xr;          // broadcast across 16 lanes
            float4 a1 = *(const float4*)(xr + 4);
            const float* wr = Wb + k * XP + tx * 8;
            float4 b0 = *(const float4*)wr;          // naturally packed n-pairs
            float4 b1 = *(const float4*)(wr + 4);
            uint64_t bp[4];
            { const uint64_t* u = (const uint64_t*)&b0; bp[0] = u[0]; bp[1] = u[1]; }
            { const uint64_t* u = (const uint64_t*)&b1; bp[2] = u[0]; bp[3] = u[1]; }
            const float aa[8] = {a0.x, a0.y, a0.z, a0.w, a1.x, a1.y, a1.z, a1.w};
            #pragma unroll
            for (int m = 0; m < 8; ++m) {
                uint64_t ad = dupf(aa[m]);
                #pragma unroll
                for (int p = 0; p < 4; ++p) ffma2(acc[m][p], ad, bp[p]);
            }
        }
        __syncthreads();
    }

    #pragma unroll
    for (int m = 0; m < 8; ++m) {
        float c[8];
        #pragma unroll
        for (int p = 0; p < 4; ++p) unpack2(acc[m][p], c[2 * p], c[2 * p + 1]);
        float* pr = g_partial + ((size_t)z * BATCH + m0 + ty * 8 + m) * 256
                    + n0 + tx * 8;
        *(float4*)pr       = make_float4(c[0], c[1], c[2], c[3]);
        *(float4*)(pr + 4) = make_float4(c[4], c[5], c[6], c[7]);
    }
}

// ------------------------------------------------------------------
// reduce: out = relu(sum_s partial + bias)
// ------------------------------------------------------------------
__global__ __launch_bounds__(256)
void reduce_kernel(const float* __restrict__ bias, float* __restrict__ out)
{
    const int g = blockIdx.x * 256 + threadIdx.x;   // float4 index
    const int m = g >> 6;
    const int nc = g & 63;
    float4 acc = ((const float4*)bias)[nc];
    #pragma unroll
    for (int ks = 0; ks < SPLITK; ++ks) {
        float4 p = ((const float4*)g_partial)[((size_t)ks * BATCH + m) * 64 + nc];
        acc.x += p.x; acc.y += p.y; acc.z += p.z; acc.w += p.w;
    }
    acc.x = fmaxf(acc.x, 0.0f); acc.y = fmaxf(acc.y, 0.0f);
    acc.z = fmaxf(acc.z, 0.0f); acc.w = fmaxf(acc.w, 0.0f);
    ((float4*)out)[(size_t)m * 64 + nc] = acc;
}

// ------------------------------------------------------------------
// launch
// ------------------------------------------------------------------
extern "C" void kernel_launch(void* const* d_in, const int* in_sizes, int n_in,
                              void* d_out, int out_size)
{
    const float* value = (const float*)d_in[0];
    const float* key_  = (const float*)d_in[1];
    const float* query = (const float*)d_in[2];
    const float* W_ff  = (const float*)d_in[4];
    const float* b_ff  = (const float*)d_in[5];

    float* out  = (float*)d_out;                 // [2048, 256]
    float* attn = out + (size_t)BATCH * 256;     // [2048, 64, 256]

    cudaFuncSetAttribute(attn_kernel,
                         cudaFuncAttributeMaxDynamicSharedMemorySize, ATTN_SMEM_BYTES);
    cudaFuncSetAttribute(ff2_kernel,
                         cudaFuncAttributeMaxDynamicSharedMemorySize, FF_SMEM_BYTES);

    attn_kernel<<<BATCH, 256, ATTN_SMEM_BYTES>>>(query, key_, value, attn);
    ff2_kernel<<<dim3(16, 2, SPLITK), 256, FF_SMEM_BYTES>>>(W_ff);
    reduce_kernel<<<512, 256>>>(b_ff, out);
}